// round 2
// baseline (speedup 1.0000x reference)
#include <cuda_runtime.h>

// Problem constants (fixed shapes)
#define T_DIM   1024
#define N_BATCH 8
#define E_DIM   1024
#define H_HEADS 16
#define D_HEAD  64
#define S_DIM   1024
#define B_HEADS 128          // N*H
#define M_ROWS  8192         // T*N
#define QKV_LD  3072
#define ROW_STRIDE 24576     // N_BATCH * QKV_LD (stride between consecutive t for fixed (n,h))

// Scratch (allocation-free: __device__ globals)
__device__ float g_qkv[(size_t)M_ROWS * QKV_LD];                 // [t*8+n][3E]   ~100 MB
__device__ float g_attn[(size_t)B_HEADS * T_DIM * S_DIM];        // [b][t][s]     ~537 MB
__device__ float g_ctx[(size_t)M_ROWS * E_DIM];                  // [t*8+n][E]    ~33 MB

// ---------------------------------------------------------------------------
// Generic fp32 GEMM core: C[m][n] = alpha * sum_k A[m*lda+k]*B[n*ldb+k] (+bias[n])
// Both operands K-contiguous ("NT" layout). BM=BN=128, BK=16, 256 threads, 8x8/thread.
// All dims assumed multiples of tile sizes (true for this problem).
// ---------------------------------------------------------------------------
template<bool HAS_BIAS>
__device__ __forceinline__ void gemm_nt_core(
    const float* __restrict__ A, int lda,
    const float* __restrict__ B, int ldb,
    const float* __restrict__ bias,
    float* __restrict__ C, int ldc,
    int K, float alpha, int m0, int n0)
{
    __shared__ float As[16][132];
    __shared__ float Bs[16][132];

    const int tid = threadIdx.x;
    const int tr  = tid >> 4;    // 0..15
    const int tc  = tid & 15;    // 0..15

    float acc[8][8];
#pragma unroll
    for (int i = 0; i < 8; i++)
#pragma unroll
        for (int j = 0; j < 8; j++) acc[i][j] = 0.f;

    for (int kk = 0; kk < K; kk += 16) {
#pragma unroll
        for (int u = 0; u < 2; u++) {
            int f    = tid + u * 256;       // 0..511 over 512 float4s per tile
            int row  = f >> 2;              // 0..127
            int col4 = (f & 3) << 2;        // 0,4,8,12
            float4 va = *reinterpret_cast<const float4*>(A + (size_t)(m0 + row) * lda + kk + col4);
            As[col4 + 0][row] = va.x;
            As[col4 + 1][row] = va.y;
            As[col4 + 2][row] = va.z;
            As[col4 + 3][row] = va.w;
            float4 vb = *reinterpret_cast<const float4*>(B + (size_t)(n0 + row) * ldb + kk + col4);
            Bs[col4 + 0][row] = vb.x;
            Bs[col4 + 1][row] = vb.y;
            Bs[col4 + 2][row] = vb.z;
            Bs[col4 + 3][row] = vb.w;
        }
        __syncthreads();
#pragma unroll
        for (int k = 0; k < 16; k++) {
            float a[8], b[8];
            *reinterpret_cast<float4*>(&a[0]) = *reinterpret_cast<const float4*>(&As[k][tr * 8]);
            *reinterpret_cast<float4*>(&a[4]) = *reinterpret_cast<const float4*>(&As[k][tr * 8 + 4]);
            *reinterpret_cast<float4*>(&b[0]) = *reinterpret_cast<const float4*>(&Bs[k][tc * 8]);
            *reinterpret_cast<float4*>(&b[4]) = *reinterpret_cast<const float4*>(&Bs[k][tc * 8 + 4]);
#pragma unroll
            for (int i = 0; i < 8; i++)
#pragma unroll
                for (int j = 0; j < 8; j++)
                    acc[i][j] = fmaf(a[i], b[j], acc[i][j]);
        }
        __syncthreads();
    }

#pragma unroll
    for (int i = 0; i < 8; i++) {
        int m = m0 + tr * 8 + i;
#pragma unroll
        for (int j = 0; j < 8; j += 4) {
            int n = n0 + tc * 8 + j;
            float4 v;
            v.x = alpha * acc[i][j + 0] + (HAS_BIAS ? bias[n + 0] : 0.f);
            v.y = alpha * acc[i][j + 1] + (HAS_BIAS ? bias[n + 1] : 0.f);
            v.z = alpha * acc[i][j + 2] + (HAS_BIAS ? bias[n + 2] : 0.f);
            v.w = alpha * acc[i][j + 3] + (HAS_BIAS ? bias[n + 3] : 0.f);
            *reinterpret_cast<float4*>(C + (size_t)m * ldc + n) = v;
        }
    }
}

// 1) QKV in-projection: g_qkv[m][f] = query[m][:]·W[f][:] + bias[f]
__global__ __launch_bounds__(256) void qkv_gemm_kernel(
    const float* __restrict__ query, const float* __restrict__ w, const float* __restrict__ bias)
{
    gemm_nt_core<true>(query, E_DIM, w, E_DIM, bias, g_qkv, QKV_LD,
                       E_DIM, 1.f, blockIdx.y * 128, blockIdx.x * 128);
}

// 2) Scores: g_attn[b][t][s] = (1/8) * q_b[t][:]·k_b[s][:]   (K = 64)
__global__ __launch_bounds__(256) void scores_kernel()
{
    int b = blockIdx.z;
    int n = b >> 4, h = b & 15;
    const float* Aq = g_qkv + n * QKV_LD + h * D_HEAD;            // q[t][d]: t*ROW_STRIDE + d
    const float* Bk = Aq + E_DIM;                                 // k[s][d]
    float* C = g_attn + (size_t)b * T_DIM * S_DIM;
    gemm_nt_core<false>(Aq, ROW_STRIDE, Bk, ROW_STRIDE, nullptr, C, S_DIM,
                        D_HEAD, 0.125f, blockIdx.y * 128, blockIdx.x * 128);
}

// 3) Row softmax over S=1024. One block (256 threads, 4 elems/thread) per row.
__global__ __launch_bounds__(256) void softmax_kernel()
{
    __shared__ float red[8];
    float* p = g_attn + (size_t)blockIdx.x * S_DIM;
    const int tid = threadIdx.x;
    const int lane = tid & 31, wid = tid >> 5;

    float4 v = *reinterpret_cast<const float4*>(p + tid * 4);
    float mx = fmaxf(fmaxf(v.x, v.y), fmaxf(v.z, v.w));
#pragma unroll
    for (int o = 16; o; o >>= 1) mx = fmaxf(mx, __shfl_xor_sync(0xffffffffu, mx, o));
    if (lane == 0) red[wid] = mx;
    __syncthreads();
    float m = red[0];
#pragma unroll
    for (int i = 1; i < 8; i++) m = fmaxf(m, red[i]);

    float e0 = __expf(v.x - m);
    float e1 = __expf(v.y - m);
    float e2 = __expf(v.z - m);
    float e3 = __expf(v.w - m);
    float s = (e0 + e1) + (e2 + e3);
#pragma unroll
    for (int o = 16; o; o >>= 1) s += __shfl_xor_sync(0xffffffffu, s, o);
    __syncthreads();               // done reading red[] from max phase
    if (lane == 0) red[wid] = s;
    __syncthreads();
    float tot = 0.f;
#pragma unroll
    for (int i = 0; i < 8; i++) tot += red[i];
    float inv = 1.0f / tot;

    float4 r = make_float4(e0 * inv, e1 * inv, e2 * inv, e3 * inv);
    *reinterpret_cast<float4*>(p + tid * 4) = r;
}

// 4) PV: g_ctx[(t*8+n)][h*64+d] = sum_s attn[b][t][s] * v_b[s][d]
//    BM=128 (t) x BN=64 (d, full head) x BK=32 (s); 256 threads, 8x4/thread.
__global__ __launch_bounds__(256) void pv_kernel()
{
    __shared__ float As[32][132];
    __shared__ float Vs[32][68];

    int b = blockIdx.z;
    int n = b >> 4, h = b & 15;
    const float* A = g_attn + (size_t)b * T_DIM * S_DIM;          // [t][s]
    const float* V = g_qkv + n * QKV_LD + 2 * E_DIM + h * D_HEAD; // v[s][d]: s*ROW_STRIDE + d
    int t0 = blockIdx.y * 128;

    const int tid = threadIdx.x;
    const int tr = tid >> 4;     // 0..15 -> 8 t-rows each
    const int tc = tid & 15;     // 0..15 -> 4 d-cols each

    float acc[8][4];
#pragma unroll
    for (int i = 0; i < 8; i++)
#pragma unroll
        for (int j = 0; j < 4; j++) acc[i][j] = 0.f;

    for (int kk = 0; kk < S_DIM; kk += 32) {
        // attn tile: 128 x 32 = 1024 float4
#pragma unroll
        for (int u = 0; u < 4; u++) {
            int f = tid + u * 256;
            int row = f >> 3;            // 0..127
            int col4 = (f & 7) << 2;     // 0..28
            float4 va = *reinterpret_cast<const float4*>(A + (size_t)(t0 + row) * S_DIM + kk + col4);
            As[col4 + 0][row] = va.x;
            As[col4 + 1][row] = va.y;
            As[col4 + 2][row] = va.z;
            As[col4 + 3][row] = va.w;
        }
        // v tile: 32 x 64 = 512 float4
#pragma unroll
        for (int u = 0; u < 2; u++) {
            int f = tid + u * 256;
            int row = f >> 4;            // 0..31
            int col4 = (f & 15) << 2;    // 0..60
            float4 vv = *reinterpret_cast<const float4*>(V + (size_t)(kk + row) * ROW_STRIDE + col4);
            *reinterpret_cast<float4*>(&Vs[row][col4]) = vv;
        }
        __syncthreads();
#pragma unroll
        for (int k = 0; k < 32; k++) {
            float a[8];
            *reinterpret_cast<float4*>(&a[0]) = *reinterpret_cast<const float4*>(&As[k][tr * 8]);
            *reinterpret_cast<float4*>(&a[4]) = *reinterpret_cast<const float4*>(&As[k][tr * 8 + 4]);
            float4 bv = *reinterpret_cast<const float4*>(&Vs[k][tc * 4]);
#pragma unroll
            for (int i = 0; i < 8; i++) {
                acc[i][0] = fmaf(a[i], bv.x, acc[i][0]);
                acc[i][1] = fmaf(a[i], bv.y, acc[i][1]);
                acc[i][2] = fmaf(a[i], bv.z, acc[i][2]);
                acc[i][3] = fmaf(a[i], bv.w, acc[i][3]);
            }
        }
        __syncthreads();
    }

#pragma unroll
    for (int i = 0; i < 8; i++) {
        int t = t0 + tr * 8 + i;
        float4 v = make_float4(acc[i][0], acc[i][1], acc[i][2], acc[i][3]);
        *reinterpret_cast<float4*>(g_ctx + ((size_t)t * N_BATCH + n) * E_DIM + h * D_HEAD + tc * 4) = v;
    }
}

// 5) Head-average of probs: avg[n][t][s] = mean_h attn[n*16+h][t][s]
__global__ __launch_bounds__(256) void avg_kernel(float* __restrict__ outAvg)
{
    int idx = blockIdx.x * 256 + threadIdx.x;    // over N*T*S/4 = 2,097,152 float4s
    int n = idx >> 18;                           // / 262144
    int rem = idx & 262143;                      // t*256 + s4
    const float* base = g_attn + (size_t)n * 16 * 1048576 + (size_t)rem * 4;
    float4 acc = make_float4(0.f, 0.f, 0.f, 0.f);
#pragma unroll
    for (int h = 0; h < 16; h++) {
        float4 v = *reinterpret_cast<const float4*>(base + (size_t)h * 1048576);
        acc.x += v.x; acc.y += v.y; acc.z += v.z; acc.w += v.w;
    }
    const float s = 1.f / 16.f;
    float4 r = make_float4(acc.x * s, acc.y * s, acc.z * s, acc.w * s);
    *reinterpret_cast<float4*>(outAvg + (size_t)idx * 4) = r;
}

// 6) Out-projection: out[m][f] = g_ctx[m][:]·Wout[f][:] + bias[f]
__global__ __launch_bounds__(256) void outproj_kernel(
    const float* __restrict__ w, const float* __restrict__ bias, float* __restrict__ out)
{
    gemm_nt_core<true>(g_ctx, E_DIM, w, E_DIM, bias, out, E_DIM,
                       E_DIM, 1.f, blockIdx.y * 128, blockIdx.x * 128);
}

extern "C" void kernel_launch(void* const* d_in, const int* in_sizes, int n_in,
                              void* d_out, int out_size)
{
    (void)in_sizes; (void)n_in; (void)out_size;
    const float* query = (const float*)d_in[0];
    // d_in[1] (key) and d_in[2] (value) are unused — the reference projects only `query`.
    const float* in_w  = (const float*)d_in[3];
    const float* in_b  = (const float*)d_in[4];
    const float* out_w = (const float*)d_in[5];
    const float* out_b = (const float*)d_in[6];
    float* out = (float*)d_out;                       // [0, 8388608): out ; [8388608, ...): avg_weights

    // 1) QKV projection: (8192 x 1024) @ (1024 x 3072)^T-ish (both K-major)
    qkv_gemm_kernel<<<dim3(QKV_LD / 128, M_ROWS / 128), 256>>>(query, in_w, in_b);

    // 2) Scores per head: 128 x (1024 x 1024 x 64)
    scores_kernel<<<dim3(S_DIM / 128, T_DIM / 128, B_HEADS), 256>>>();

    // 3) Softmax over each of 131072 rows
    softmax_kernel<<<B_HEADS * T_DIM, 256>>>();

    // 4) PV per head: 128 x (1024 x 64 x 1024)
    pv_kernel<<<dim3(1, T_DIM / 128, B_HEADS), 256>>>();

    // 5) Head-averaged attention weights -> second output
    avg_kernel<<<(N_BATCH * T_DIM * S_DIM / 4) / 256, 256>>>(out + (size_t)M_ROWS * E_DIM);

    // 6) Output projection -> first output
    outproj_kernel<<<dim3(E_DIM / 128, M_ROWS / 128), 256>>>(out_w, out_b, out);
}

// round 6
// speedup vs baseline: 2.0075x; 2.0075x over previous
#include <cuda_runtime.h>
#include <cuda_bf16.h>
#include <cstdint>

// Shapes (fixed)
#define T_DIM   1024
#define N_BATCH 8
#define E_DIM   1024
#define H_HEADS 16
#define D_HEAD  64
#define B_HEADS 128
#define M_ROWS  8192
#define QKV_LD  3072
#define ROW_STRIDE 24576   // 8*3072

typedef __nv_bfloat16 bf16;

// ---------------- scratch (allocation-free) ----------------
__device__ bf16  g_qh [(size_t)M_ROWS * E_DIM];
__device__ bf16  g_ql [(size_t)M_ROWS * E_DIM];
__device__ bf16  g_wih[(size_t)QKV_LD * E_DIM];
__device__ bf16  g_wil[(size_t)QKV_LD * E_DIM];
__device__ bf16  g_woh[(size_t)E_DIM * E_DIM];
__device__ bf16  g_wol[(size_t)E_DIM * E_DIM];
__device__ float g_qkv [(size_t)M_ROWS * QKV_LD];
__device__ bf16  g_qkvh[(size_t)M_ROWS * QKV_LD];
__device__ bf16  g_qkvl[(size_t)M_ROWS * QKV_LD];
__device__ bf16  g_vth[(size_t)N_BATCH * E_DIM * T_DIM];   // [n][d][s]
__device__ bf16  g_vtl[(size_t)N_BATCH * E_DIM * T_DIM];
__device__ float g_attn[(size_t)B_HEADS * T_DIM * T_DIM];
__device__ bf16  g_ph  [(size_t)B_HEADS * T_DIM * T_DIM];
__device__ bf16  g_pl  [(size_t)B_HEADS * T_DIM * T_DIM];
__device__ float g_ctx [(size_t)M_ROWS * E_DIM];
__device__ bf16  g_ch [(size_t)M_ROWS * E_DIM];
__device__ bf16  g_cl [(size_t)M_ROWS * E_DIM];

#define DEVFN __device__ __forceinline__

DEVFN uint32_t smem_u32(const void* p) {
    uint32_t a;
    asm("{ .reg .u64 t; cvta.to.shared.u64 t, %1; cvt.u32.u64 %0, t; }" : "=r"(a) : "l"(p));
    return a;
}
DEVFN void cpa16(uint32_t s, const void* g) {
    asm volatile("cp.async.cg.shared.global [%0], [%1], 16;" :: "r"(s), "l"(g));
}
DEVFN void cp_commit() { asm volatile("cp.async.commit_group;" ::: "memory"); }
template<int N> DEVFN void cp_wait() { asm volatile("cp.async.wait_group %0;" :: "n"(N) : "memory"); }
DEVFN uint32_t lds32(uint32_t a) {
    uint32_t v;
    asm volatile("ld.shared.b32 %0, [%1];" : "=r"(v) : "r"(a));
    return v;
}
DEVFN void mma16816(float* c, const uint32_t* a, const uint32_t* b) {
    asm volatile(
        "mma.sync.aligned.m16n8k16.row.col.f32.bf16.bf16.f32 "
        "{%0,%1,%2,%3}, {%4,%5,%6,%7}, {%8,%9}, {%0,%1,%2,%3};"
        : "+f"(c[0]), "+f"(c[1]), "+f"(c[2]), "+f"(c[3])
        : "r"(a[0]), "r"(a[1]), "r"(a[2]), "r"(a[3]), "r"(b[0]), "r"(b[1]));
}

// ---------------------------------------------------------------------------
// Split-bf16 NT GEMM core on mma.sync: C[m][n] = alpha*sum_k A[m][k]B[n][k] (+bias)
// CTA tile 128 x BN, BK=32, 8 warps of WM x WN. Padded smem pitch 80B.
// ---------------------------------------------------------------------------
template<int BN, int WM, int WN, bool HAS_BIAS>
DEVFN void gemm_core(const bf16* __restrict__ Ah, const bf16* __restrict__ Al, int lda,
                     const bf16* __restrict__ Bh, const bf16* __restrict__ Bl, int ldb,
                     const float* __restrict__ bias, float alpha,
                     float* __restrict__ C, int ldc, int K, int m0, int n0, char* smem)
{
    constexpr int PITCH = 80;            // bytes per k-row (32 bf16 data + pad)
    constexpr int ASZ = 128 * PITCH;     // 10240
    constexpr int BSZ = BN  * PITCH;
    constexpr int STAGE = 2 * ASZ + 2 * BSZ;
    const int tid = threadIdx.x;
    const uint32_t sbase = smem_u32(smem);

    auto load_stage = [&](int st, int kk) {
        uint32_t s0 = sbase + st * STAGE;
#pragma unroll
        for (int i = 0; i < 2; ++i) {               // 512 A-chunks / 256 thr
            int id = tid + i * 256;
            int row = id >> 2, ck = id & 3;
            uint32_t so = s0 + row * PITCH + ck * 16;
            size_t go = (size_t)(m0 + row) * lda + kk + ck * 8;
            cpa16(so, Ah + go);
            cpa16(so + ASZ, Al + go);
        }
#pragma unroll
        for (int i = 0; i < (BN * 4) / 256; ++i) {
            int id = tid + i * 256;
            int row = id >> 2, ck = id & 3;
            uint32_t so = s0 + 2 * ASZ + row * PITCH + ck * 16;
            size_t go = (size_t)(n0 + row) * ldb + kk + ck * 8;
            cpa16(so, Bh + go);
            cpa16(so + BSZ, Bl + go);
        }
    };

    constexpr int WGM = 128 / WM;
    constexpr int MT = WM / 16, NT = WN / 8;
    const int lane = tid & 31, wid = tid >> 5;
    const int wm = wid % WGM, wn = wid / WGM;
    const int r0 = lane >> 2, c0 = (lane & 3) * 2;

    float acc[MT][NT][4];
#pragma unroll
    for (int i = 0; i < MT; i++)
#pragma unroll
        for (int j = 0; j < NT; j++) {
            acc[i][j][0] = 0.f; acc[i][j][1] = 0.f; acc[i][j][2] = 0.f; acc[i][j][3] = 0.f;
        }

    const int NC = K >> 5;
    load_stage(0, 0);
    cp_commit();

    for (int c = 0; c < NC; ++c) {
        if (c + 1 < NC) { load_stage((c + 1) & 1, (c + 1) * 32); cp_commit(); cp_wait<1>(); }
        else            { cp_wait<0>(); }
        __syncthreads();

        const uint32_t sA = sbase + (c & 1) * STAGE;
        const uint32_t sB = sA + 2 * ASZ;
#pragma unroll
        for (int ks = 0; ks < 2; ++ks) {
            uint32_t ah[MT][4], al[MT][4], bh[NT][2], bl[NT][2];
#pragma unroll
            for (int mt = 0; mt < MT; ++mt) {
                uint32_t a0 = sA + (wm * WM + mt * 16 + r0) * PITCH + (ks * 16 + c0) * 2;
                ah[mt][0] = lds32(a0);
                ah[mt][1] = lds32(a0 + 8 * PITCH);
                ah[mt][2] = lds32(a0 + 16);
                ah[mt][3] = lds32(a0 + 8 * PITCH + 16);
                al[mt][0] = lds32(a0 + ASZ);
                al[mt][1] = lds32(a0 + ASZ + 8 * PITCH);
                al[mt][2] = lds32(a0 + ASZ + 16);
                al[mt][3] = lds32(a0 + ASZ + 8 * PITCH + 16);
            }
#pragma unroll
            for (int nt = 0; nt < NT; ++nt) {
                uint32_t b0 = sB + (wn * WN + nt * 8 + r0) * PITCH + (ks * 16 + c0) * 2;
                bh[nt][0] = lds32(b0);
                bh[nt][1] = lds32(b0 + 16);
                bl[nt][0] = lds32(b0 + BSZ);
                bl[nt][1] = lds32(b0 + BSZ + 16);
            }
#pragma unroll
            for (int mt = 0; mt < MT; ++mt)
#pragma unroll
                for (int nt = 0; nt < NT; ++nt) {
                    mma16816(acc[mt][nt], ah[mt], bh[nt]);
                    mma16816(acc[mt][nt], ah[mt], bl[nt]);
                    mma16816(acc[mt][nt], al[mt], bh[nt]);
                }
        }
        __syncthreads();
    }

    // epilogue
#pragma unroll
    for (int mt = 0; mt < MT; ++mt) {
#pragma unroll
        for (int nt = 0; nt < NT; ++nt) {
            int row = m0 + wm * WM + mt * 16 + r0;
            int col = n0 + wn * WN + nt * 8 + c0;
            float bx = HAS_BIAS ? bias[col] : 0.f;
            float by = HAS_BIAS ? bias[col + 1] : 0.f;
            float2 v0 = make_float2(alpha * acc[mt][nt][0] + bx, alpha * acc[mt][nt][1] + by);
            float2 v1 = make_float2(alpha * acc[mt][nt][2] + bx, alpha * acc[mt][nt][3] + by);
            *reinterpret_cast<float2*>(C + (size_t)row * ldc + col) = v0;
            *reinterpret_cast<float2*>(C + (size_t)(row + 8) * ldc + col) = v1;
        }
    }
}

#define SMEM_128 (2 * (2 * 128 * 80 + 2 * 128 * 80))   // 81920
#define SMEM_64  (2 * (2 * 128 * 80 + 2 * 64 * 80))    // 61440

// ---- 1) QKV projection: g_qkv = query @ in_w^T + in_b ----
__global__ __launch_bounds__(256) void k_qkv(const float* __restrict__ bias) {
    extern __shared__ char smem[];
    gemm_core<128, 64, 32, true>(g_qh, g_ql, E_DIM, g_wih, g_wil, E_DIM,
                                 bias, 1.f, g_qkv, QKV_LD, E_DIM,
                                 blockIdx.y * 128, blockIdx.x * 128, smem);
}

// ---- 2) scores: g_attn[b][t][s] = 0.125 * q.k ----
__global__ __launch_bounds__(256) void k_scores() {
    extern __shared__ char smem[];
    const int hb = blockIdx.z, n = hb >> 4, h = hb & 15;
    const bf16* Ah = g_qkvh + n * QKV_LD + h * D_HEAD;
    const bf16* Al = g_qkvl + n * QKV_LD + h * D_HEAD;
    float* C = g_attn + ((size_t)hb << 20);
    gemm_core<128, 64, 32, false>(Ah, Al, ROW_STRIDE, Ah + E_DIM, Al + E_DIM, ROW_STRIDE,
                                  nullptr, 0.125f, C, T_DIM, D_HEAD,
                                  blockIdx.y * 128, blockIdx.x * 128, smem);
}

// ---- 3) PV: g_ctx[t][h*64+d] = sum_s p[t][s] vt[d][s] ----
__global__ __launch_bounds__(256) void k_pv() {
    extern __shared__ char smem[];
    const int hb = blockIdx.y, n = hb >> 4, h = hb & 15;
    const bf16* Ah = g_ph + ((size_t)hb << 20);
    const bf16* Al = g_pl + ((size_t)hb << 20);
    const bf16* Bh = g_vth + ((size_t)n * E_DIM + h * D_HEAD) * T_DIM;
    const bf16* Bl = g_vtl + ((size_t)n * E_DIM + h * D_HEAD) * T_DIM;
    float* C = g_ctx + (size_t)n * E_DIM + h * D_HEAD;
    gemm_core<64, 32, 32, false>(Ah, Al, T_DIM, Bh, Bl, T_DIM,
                                 nullptr, 1.f, C, N_BATCH * E_DIM, T_DIM,
                                 blockIdx.x * 128, 0, smem);
}

// ---- 4) out projection ----
__global__ __launch_bounds__(256) void k_out(const float* __restrict__ bias, float* __restrict__ out) {
    extern __shared__ char smem[];
    gemm_core<128, 64, 32, true>(g_ch, g_cl, E_DIM, g_woh, g_wol, E_DIM,
                                 bias, 1.f, out, E_DIM, E_DIM,
                                 blockIdx.y * 128, blockIdx.x * 128, smem);
}

// ---------------- split fp32 -> (hi, lo) bf16 ----------------
__global__ __launch_bounds__(256) void split_kernel(
    const float* __restrict__ x, bf16* __restrict__ h, bf16* __restrict__ l) {
    size_t i = (size_t)blockIdx.x * 256 + threadIdx.x;
    float4 v = reinterpret_cast<const float4*>(x)[i];
    bf16 h0 = __float2bfloat16(v.x), h1 = __float2bfloat16(v.y);
    bf16 h2 = __float2bfloat16(v.z), h3 = __float2bfloat16(v.w);
    bf16 l0 = __float2bfloat16(v.x - __bfloat162float(h0));
    bf16 l1 = __float2bfloat16(v.y - __bfloat162float(h1));
    bf16 l2 = __float2bfloat16(v.z - __bfloat162float(h2));
    bf16 l3 = __float2bfloat16(v.w - __bfloat162float(h3));
    union { __nv_bfloat162 b[2]; uint2 u; } H, L;
    H.b[0] = __halves2bfloat162(h0, h1); H.b[1] = __halves2bfloat162(h2, h3);
    L.b[0] = __halves2bfloat162(l0, l1); L.b[1] = __halves2bfloat162(l2, l3);
    *reinterpret_cast<uint2*>(h + i * 4) = H.u;
    *reinterpret_cast<uint2*>(l + i * 4) = L.u;
}

// ---------------- V transpose: g_vt[n][d][s] = split(qkv_v[s][d]) ----------------
__global__ __launch_bounds__(256) void vt_kernel() {
    __shared__ float tile[32][33];
    const int d0 = blockIdx.x * 32, s0 = blockIdx.y * 32, n = blockIdx.z;
    const int tx = threadIdx.x, ty = threadIdx.y;   // block (32, 8)
#pragma unroll
    for (int j = 0; j < 32; j += 8) {
        int s = s0 + ty + j;
        tile[ty + j][tx] = g_qkv[((size_t)s * N_BATCH + n) * QKV_LD + 2 * E_DIM + d0 + tx];
    }
    __syncthreads();
#pragma unroll
    for (int j = 0; j < 32; j += 8) {
        int d = d0 + ty + j;
        float v = tile[tx][ty + j];
        bf16 h = __float2bfloat16(v);
        bf16 l = __float2bfloat16(v - __bfloat162float(h));
        size_t o = ((size_t)n * E_DIM + d) * T_DIM + s0 + tx;
        g_vth[o] = h;
        g_vtl[o] = l;
    }
}

// ---------------- softmax: fp32 scores -> (p_hi, p_lo) ----------------
__global__ __launch_bounds__(256) void softmax_kernel() {
    __shared__ float red[8];
    const size_t row = blockIdx.x;
    const float* p = g_attn + row * 1024;
    const int tid = threadIdx.x, lane = tid & 31, wid = tid >> 5;

    float4 v = *reinterpret_cast<const float4*>(p + tid * 4);
    float mx = fmaxf(fmaxf(v.x, v.y), fmaxf(v.z, v.w));
#pragma unroll
    for (int o = 16; o; o >>= 1) mx = fmaxf(mx, __shfl_xor_sync(0xffffffffu, mx, o));
    if (lane == 0) red[wid] = mx;
    __syncthreads();
    float m = red[0];
#pragma unroll
    for (int i = 1; i < 8; i++) m = fmaxf(m, red[i]);

    float e0 = __expf(v.x - m), e1 = __expf(v.y - m);
    float e2 = __expf(v.z - m), e3 = __expf(v.w - m);
    float s = (e0 + e1) + (e2 + e3);
#pragma unroll
    for (int o = 16; o; o >>= 1) s += __shfl_xor_sync(0xffffffffu, s, o);
    __syncthreads();
    if (lane == 0) red[wid] = s;
    __syncthreads();
    float tot = 0.f;
#pragma unroll
    for (int i = 0; i < 8; i++) tot += red[i];
    float inv = 1.0f / tot;

    float p0 = e0 * inv, p1 = e1 * inv, p2 = e2 * inv, p3 = e3 * inv;
    bf16 h0 = __float2bfloat16(p0), h1 = __float2bfloat16(p1);
    bf16 h2 = __float2bfloat16(p2), h3 = __float2bfloat16(p3);
    bf16 l0 = __float2bfloat16(p0 - __bfloat162float(h0));
    bf16 l1 = __float2bfloat16(p1 - __bfloat162float(h1));
    bf16 l2 = __float2bfloat16(p2 - __bfloat162float(h2));
    bf16 l3 = __float2bfloat16(p3 - __bfloat162float(h3));
    union { __nv_bfloat162 b[2]; uint2 u; } H, L;
    H.b[0] = __halves2bfloat162(h0, h1); H.b[1] = __halves2bfloat162(h2, h3);
    L.b[0] = __halves2bfloat162(l0, l1); L.b[1] = __halves2bfloat162(l2, l3);
    *reinterpret_cast<uint2*>(g_ph + row * 1024 + tid * 4) = H.u;
    *reinterpret_cast<uint2*>(g_pl + row * 1024 + tid * 4) = L.u;
}

// ---------------- avg over heads ----------------
__global__ __launch_bounds__(256) void avg_kernel(float* __restrict__ outAvg) {
    const int idx = blockIdx.x * 256 + threadIdx.x;
    const int n = idx >> 18;
    const int rem = idx & 262143;
    float4 acc = make_float4(0.f, 0.f, 0.f, 0.f);
#pragma unroll
    for (int h = 0; h < 16; h++) {
        const size_t base = ((size_t)(n * 16 + h) << 20) + (size_t)rem * 4;
        union { uint2 u; __nv_bfloat162 b[2]; } Hv, Lv;
        Hv.u = *reinterpret_cast<const uint2*>(g_ph + base);
        Lv.u = *reinterpret_cast<const uint2*>(g_pl + base);
        float2 a0 = __bfloat1622float2(Hv.b[0]), a1 = __bfloat1622float2(Hv.b[1]);
        float2 b0 = __bfloat1622float2(Lv.b[0]), b1 = __bfloat1622float2(Lv.b[1]);
        acc.x += a0.x + b0.x; acc.y += a0.y + b0.y;
        acc.z += a1.x + b1.x; acc.w += a1.y + b1.y;
    }
    const float sc = 1.f / 16.f;
    *reinterpret_cast<float4*>(outAvg + (size_t)idx * 4) =
        make_float4(acc.x * sc, acc.y * sc, acc.z * sc, acc.w * sc);
}

// ---------------- host ----------------
extern "C" void kernel_launch(void* const* d_in, const int* in_sizes, int n_in,
                              void* d_out, int out_size) {
    (void)in_sizes; (void)n_in; (void)out_size;
    const float* query = (const float*)d_in[0];
    const float* in_w  = (const float*)d_in[3];
    const float* in_b  = (const float*)d_in[4];
    const float* out_w = (const float*)d_in[5];
    const float* out_b = (const float*)d_in[6];
    float* out = (float*)d_out;
    float* avg = out + (size_t)M_ROWS * E_DIM;

    void *qh, *ql, *wih, *wil, *woh, *wol, *qkv, *qkvh, *qkvl, *ctx, *ch, *cl;
    cudaGetSymbolAddress(&qh,  g_qh);  cudaGetSymbolAddress(&ql,  g_ql);
    cudaGetSymbolAddress(&wih, g_wih); cudaGetSymbolAddress(&wil, g_wil);
    cudaGetSymbolAddress(&woh, g_woh); cudaGetSymbolAddress(&wol, g_wol);
    cudaGetSymbolAddress(&qkv, g_qkv);
    cudaGetSymbolAddress(&qkvh, g_qkvh); cudaGetSymbolAddress(&qkvl, g_qkvl);
    cudaGetSymbolAddress(&ctx, g_ctx);
    cudaGetSymbolAddress(&ch,  g_ch);  cudaGetSymbolAddress(&cl,  g_cl);

    cudaFuncSetAttribute(k_qkv,    cudaFuncAttributeMaxDynamicSharedMemorySize, SMEM_128);
    cudaFuncSetAttribute(k_scores, cudaFuncAttributeMaxDynamicSharedMemorySize, SMEM_128);
    cudaFuncSetAttribute(k_pv,     cudaFuncAttributeMaxDynamicSharedMemorySize, SMEM_64);
    cudaFuncSetAttribute(k_out,    cudaFuncAttributeMaxDynamicSharedMemorySize, SMEM_128);

    // splits of inputs
    split_kernel<<<(M_ROWS * E_DIM / 4) / 256, 256>>>(query, (bf16*)qh, (bf16*)ql);
    split_kernel<<<(QKV_LD * E_DIM / 4) / 256, 256>>>(in_w, (bf16*)wih, (bf16*)wil);
    split_kernel<<<(E_DIM * E_DIM / 4) / 256, 256>>>(out_w, (bf16*)woh, (bf16*)wol);

    // 1) QKV projection (8192 x 3072, K=1024)
    k_qkv<<<dim3(QKV_LD / 128, M_ROWS / 128), 256, SMEM_128>>>(in_b);

    // 2) split qkv (q/k sections used); transpose+split V
    split_kernel<<<((size_t)M_ROWS * QKV_LD / 4) / 256, 256>>>(
        (const float*)qkv, (bf16*)qkvh, (bf16*)qkvl);
    vt_kernel<<<dim3(E_DIM / 32, T_DIM / 32, N_BATCH), dim3(32, 8)>>>();

    // 3) scores = 0.125 * Q K^T -> fp32
    k_scores<<<dim3(T_DIM / 128, T_DIM / 128, B_HEADS), 256, SMEM_128>>>();

    // 4) softmax -> (p_hi, p_lo)
    softmax_kernel<<<B_HEADS * T_DIM, 256>>>();

    // 5) head-averaged weights -> second output
    avg_kernel<<<(N_BATCH * T_DIM * T_DIM / 4) / 256, 256>>>(avg);

    // 6) PV -> g_ctx
    k_pv<<<dim3(T_DIM / 128, B_HEADS), 256, SMEM_64>>>();

    // 7) split ctx; out-projection -> first output
    split_kernel<<<(M_ROWS * E_DIM / 4) / 256, 256>>>((const float*)ctx, (bf16*)ch, (bf16*)cl);
    k_out<<<dim3(E_DIM / 128, M_ROWS / 128), 256, SMEM_128>>>(out_b, out);
}